// round 16
// baseline (speedup 1.0000x reference)
#include <cuda_runtime.h>
#include <cuda_bf16.h>
#include <cuda_fp16.h>
#include <math.h>

#define N_NODES 100000
#define N_EDGES 1600000
#define DIMF    128
#define OUTD_F  40
#define SCAN_B  1024
#define NB_SCAN 98   // ceil(100000/1024)

// ---------------- scratch (device globals; no allocation allowed) ----------
__device__ int   g_is64;
__device__ int   g_deg[N_NODES];
__device__ float g_invdeg[N_NODES];
__device__ int   g_off[N_NODES + 1];
__device__ int   g_cursor[N_NODES];
__device__ int   g_bsums[NB_SCAN];
__device__ int   g_csc[N_EDGES];
__device__ __align__(16) unsigned short g_Ub[(size_t)N_NODES * DIMF]; // X@Wl^T, bf16 bits
__device__ __align__(16) float  g_V [(size_t)N_NODES * DIMF];          // X@Wr^T + b
__device__ __align__(16) __half g_uh[(size_t)N_NODES * OUTD_F];        // layer2: h1@Wl2^T
__device__ __align__(16) float  g_v [(size_t)N_NODES * OUTD_F];        // layer2: h1@Wr2^T + b2
// activations + weights: single bf16 copies; W stacked [Wl;Wr] = 256 rows
__device__ __align__(16) __nv_bfloat16 g_xhi[(size_t)N_NODES * DIMF];
__device__ __align__(16) __nv_bfloat16 g_W0[2*DIMF*DIMF];
__device__ __align__(16) __nv_bfloat16 g_W1[2*DIMF*DIMF];
__device__ __align__(16) __nv_bfloat16 g_W2[2*OUTD_F*DIMF];

__device__ __forceinline__ int edge_at(const int* __restrict__ e32, int i) {
    return g_is64 ? e32[2 * i] : e32[i];
}
__device__ __forceinline__ float bf_lo(unsigned w) { return __uint_as_float(w << 16); }
__device__ __forceinline__ float bf_hi(unsigned w) { return __uint_as_float(w & 0xFFFF0000u); }
__device__ __forceinline__ unsigned bf_pack(float a, float b) {
    return (unsigned)__bfloat16_as_ushort(__float2bfloat16(a)) |
           ((unsigned)__bfloat16_as_ushort(__float2bfloat16(b)) << 16);
}

// ---------------- dtype detection ------------------------------------------
__global__ void k_detect(const int* __restrict__ e32) {
    __shared__ int nonzero;
    if (threadIdx.x == 0) nonzero = 0;
    __syncthreads();
    for (int i = threadIdx.x; i < 1024; i += blockDim.x)
        if (e32[2 * i + 1] != 0) nonzero = 1;
    __syncthreads();
    if (threadIdx.x == 0) g_is64 = (nonzero == 0);
}

// ---------------- graph preprocessing --------------------------------------
__global__ void k_zero_deg() {
    int i = blockIdx.x * blockDim.x + threadIdx.x;
    if (i < N_NODES) g_deg[i] = 0;
}

__global__ void k_hist(const int* __restrict__ e32) {
    int e = blockIdx.x * blockDim.x + threadIdx.x;
    if (e < N_EDGES) {
        int d = edge_at(e32, N_EDGES + e);
        if ((unsigned)d < N_NODES) atomicAdd(&g_deg[d], 1);
    }
}

__global__ void k_scan1() {
    __shared__ int sh[SCAN_B];
    int t = threadIdx.x;
    int i = blockIdx.x * SCAN_B + t;
    int v = (i < N_NODES) ? g_deg[i] : 0;
    sh[t] = v;
    __syncthreads();
    for (int s = 1; s < SCAN_B; s <<= 1) {
        int prev = (t >= s) ? sh[t - s] : 0;
        __syncthreads();
        sh[t] += prev;
        __syncthreads();
    }
    if (i < N_NODES) g_off[i] = sh[t] - v;
    if (t == SCAN_B - 1) g_bsums[blockIdx.x] = sh[t];
}

__global__ void k_scan2() {
    __shared__ int sh[128];
    int t = threadIdx.x;
    int v = (t < NB_SCAN) ? g_bsums[t] : 0;
    sh[t] = v;
    __syncthreads();
#pragma unroll
    for (int s = 1; s < 128; s <<= 1) {
        int prev = (t >= s) ? sh[t - s] : 0;
        __syncthreads();
        sh[t] += prev;
        __syncthreads();
    }
    if (t < NB_SCAN) g_bsums[t] = sh[t] - v;   // exclusive
}

__global__ void k_scan3() {
    int i = blockIdx.x * blockDim.x + threadIdx.x;
    if (i < N_NODES) {
        int o = g_off[i] + g_bsums[i >> 10];
        g_off[i] = o;
        g_cursor[i] = o;
        int d = g_deg[i];
        g_invdeg[i] = 1.0f / (float)(d > 1 ? d : 1);
    }
    if (i == 0) g_off[N_NODES] = N_EDGES;
}

__global__ void k_fill_csc(const int* __restrict__ e32) {
    int e = blockIdx.x * blockDim.x + threadIdx.x;
    if (e < N_EDGES) {
        int s = edge_at(e32, e);
        int d = edge_at(e32, N_EDGES + e);
        if ((unsigned)s < N_NODES && (unsigned)d < N_NODES) {
            int p = atomicAdd(&g_cursor[d], 1);
            g_csc[p] = s;
        }
    }
}

// ---------------- weight rounding: ALL layers, one launch, stacked ----------
__global__ void k_round_w(const float* __restrict__ Wl0, const float* __restrict__ Wr0,
                          const float* __restrict__ Wl1, const float* __restrict__ Wr1,
                          const float* __restrict__ Wl2, const float* __restrict__ Wr2) {
    int i = blockIdx.x * blockDim.x + threadIdx.x;
    int n01 = DIMF * DIMF;
    if (i < n01) {
        g_W0[i]       = __float2bfloat16(Wl0[i]);
        g_W0[n01 + i] = __float2bfloat16(Wr0[i]);
        g_W1[i]       = __float2bfloat16(Wl1[i]);
        g_W1[n01 + i] = __float2bfloat16(Wr1[i]);
    }
    if (i < OUTD_F * DIMF) {
        g_W2[i]                 = __float2bfloat16(Wl2[i]);
        g_W2[OUTD_F * DIMF + i] = __float2bfloat16(Wr2[i]);
    }
}

// ---------------- tensor-core GEMM ------------------------------------------
__device__ __forceinline__ void mma_bf16(float* d, const unsigned* a, unsigned b0, unsigned b1) {
    asm volatile(
        "mma.sync.aligned.m16n8k16.row.col.f32.bf16.bf16.f32 "
        "{%0,%1,%2,%3}, {%4,%5,%6,%7}, {%8,%9}, {%0,%1,%2,%3};\n"
        : "+f"(d[0]), "+f"(d[1]), "+f"(d[2]), "+f"(d[3])
        : "r"(a[0]), "r"(a[1]), "r"(a[2]), "r"(a[3]), "r"(b0), "r"(b1));
}

// layers 0/1 FUSED: [U|V] = X @ [Wl;Wr]^T in one kernel.
// warps: mw=wid&3 (M groups of 32 rows), nw=wid>>2 (0 -> U cols, 1 -> V cols).
// single-pass bf16. FP32A: layer 0 reads fp32 x directly.
template <bool FP32A>
__global__ void __launch_bounds__(256) k_gemm_l01(const float* __restrict__ xin,
                                                  const float* __restrict__ bias, int layer) {
    constexpr int WROWS = 256;             // stacked Wl (128) + Wr (128)
    constexpr int MT = 2, NT = 16, STR = 20;

    __shared__ __align__(16) unsigned sAh[128 * STR];
    __shared__ __align__(16) unsigned sWh[WROWS * STR];

    const unsigned* Ah = (const unsigned*)g_xhi;
    const unsigned* Wh = (const unsigned*)(layer == 0 ? g_W0 : g_W1);

    int tid  = threadIdx.x;
    int wid  = tid >> 5, lane = tid & 31;
    int mw   = wid & 3, nw = wid >> 2;     // nw in {0,1}
    int row0 = blockIdx.x * 128;
    int lg   = lane >> 2, lt = lane & 3;

    float acc[MT][NT][4];
#pragma unroll
    for (int m = 0; m < MT; m++)
#pragma unroll
        for (int n = 0; n < NT; n++)
#pragma unroll
            for (int q = 0; q < 4; q++) acc[m][n][q] = 0.f;

#pragma unroll 1
    for (int kt = 0; kt < 4; kt++) {
        int kw = kt * 16;

        if (FP32A) {
#pragma unroll
            for (int i = tid; i < 1024; i += 256) {
                int r = i >> 3, q = (i & 7) * 4;
                float4 v = make_float4(0.f, 0.f, 0.f, 0.f);
                if (row0 + r < N_NODES)
                    v = *(const float4*)(xin + (size_t)(row0 + r) * DIMF + kt * 32 + q);
                int wq = q >> 1;
                sAh[r * STR + wq]     = bf_pack(v.x, v.y);
                sAh[r * STR + wq + 1] = bf_pack(v.z, v.w);
            }
        } else {
#pragma unroll
            for (int i = tid; i < 128 * 4; i += 256) {
                int r = i >> 2, q = (i & 3) * 4;
                uint4 vh = make_uint4(0, 0, 0, 0);
                if (row0 + r < N_NODES)
                    vh = *(const uint4*)(Ah + (size_t)(row0 + r) * 64 + kw + q);
                *(uint4*)(sAh + r * STR + q) = vh;
            }
        }
        // W tile: 256 rows x 16 words = 1024 uint4, 4 per thread
#pragma unroll
        for (int i = tid; i < WROWS * 4; i += 256) {
            int r = i >> 2, q = (i & 3) * 4;
            *(uint4*)(sWh + r * STR + q) = *(const uint4*)(Wh + (size_t)r * 64 + kw + q);
        }
        __syncthreads();

#pragma unroll
        for (int ks = 0; ks < 2; ks++) {
            int wb = ks * 8;
            unsigned ah[MT][4];
#pragma unroll
            for (int m = 0; m < MT; m++) {
                int rr = (mw * MT + m) * 16 + lg;
                ah[m][0] = sAh[rr * STR + wb + lt];
                ah[m][1] = sAh[(rr + 8) * STR + wb + lt];
                ah[m][2] = sAh[rr * STR + wb + 4 + lt];
                ah[m][3] = sAh[(rr + 8) * STR + wb + 4 + lt];
            }
#pragma unroll
            for (int n = 0; n < NT; n++) {
                int nr = nw * 128 + n * 8 + lg;
                unsigned bh0 = sWh[nr * STR + wb + lt];
                unsigned bh1 = sWh[nr * STR + wb + 4 + lt];
#pragma unroll
                for (int m = 0; m < MT; m++)
                    mma_bf16(acc[m][n], ah[m], bh0, bh1);
            }
        }
        __syncthreads();
    }

#pragma unroll
    for (int m = 0; m < MT; m++) {
        int r = row0 + (mw * MT + m) * 16 + lg;
#pragma unroll
        for (int n = 0; n < NT; n++) {
            int c = n * 8 + lt * 2;        // column within the 128-wide half
#pragma unroll
            for (int h = 0; h < 2; h++) {
                int rr = r + h * 8;
                if (rr >= N_NODES) continue;
                float v0 = acc[m][n][h * 2], v1 = acc[m][n][h * 2 + 1];
                if (nw) {
                    g_V[(size_t)rr * DIMF + c]     = v0 + bias[c];
                    g_V[(size_t)rr * DIMF + c + 1] = v1 + bias[c + 1];
                } else {
                    *(unsigned*)(g_Ub + (size_t)rr * DIMF + c) = bf_pack(v0, v1);
                }
            }
        }
    }
}

// layer 2: [u|v] = h1 @ [Wl2;Wr2]^T; u -> fp16, v -> f32 + bias. single-pass.
__global__ void __launch_bounds__(256) k_gemm2(const float* __restrict__ bias) {
    constexpr int OUTD = 80;
    constexpr int MT = 2, NT = 5, STR = 20;

    __shared__ __align__(16) unsigned sAh[128 * STR];
    __shared__ __align__(16) unsigned sWh[OUTD * STR];

    int tid  = threadIdx.x;
    int wid  = tid >> 5, lane = tid & 31;
    int mw   = wid & 3, nw = wid >> 2;
    int row0 = blockIdx.x * 128;
    int lg   = lane >> 2, lt = lane & 3;

    float acc[MT][NT][4];
#pragma unroll
    for (int m = 0; m < MT; m++)
#pragma unroll
        for (int n = 0; n < NT; n++)
#pragma unroll
            for (int q = 0; q < 4; q++) acc[m][n][q] = 0.f;

    const unsigned* Ah = (const unsigned*)g_xhi;
    const unsigned* Wh = (const unsigned*)g_W2;

#pragma unroll 1
    for (int kt = 0; kt < 4; kt++) {
        int kw = kt * 16;

#pragma unroll
        for (int i = tid; i < 128 * 4; i += 256) {
            int r = i >> 2, q = (i & 3) * 4;
            uint4 vh = make_uint4(0, 0, 0, 0);
            if (row0 + r < N_NODES)
                vh = *(const uint4*)(Ah + (size_t)(row0 + r) * 64 + kw + q);
            *(uint4*)(sAh + r * STR + q) = vh;
        }
        for (int i = tid; i < OUTD * 4; i += 256) {
            int r = i >> 2, q = (i & 3) * 4;
            *(uint4*)(sWh + r * STR + q) = *(const uint4*)(Wh + (size_t)r * 64 + kw + q);
        }
        __syncthreads();

#pragma unroll
        for (int ks = 0; ks < 2; ks++) {
            int wb = ks * 8;
            unsigned ah[MT][4];
#pragma unroll
            for (int m = 0; m < MT; m++) {
                int rr = (mw * MT + m) * 16 + lg;
                ah[m][0] = sAh[rr * STR + wb + lt];
                ah[m][1] = sAh[(rr + 8) * STR + wb + lt];
                ah[m][2] = sAh[rr * STR + wb + 4 + lt];
                ah[m][3] = sAh[(rr + 8) * STR + wb + 4 + lt];
            }
#pragma unroll
            for (int n = 0; n < NT; n++) {
                int nr = nw * NT * 8 + n * 8 + lg;
                unsigned bh0 = sWh[nr * STR + wb + lt];
                unsigned bh1 = sWh[nr * STR + wb + 4 + lt];
#pragma unroll
                for (int m = 0; m < MT; m++)
                    mma_bf16(acc[m][n], ah[m], bh0, bh1);
            }
        }
        __syncthreads();
    }

#pragma unroll
    for (int m = 0; m < MT; m++) {
        int r = row0 + (mw * MT + m) * 16 + lg;
#pragma unroll
        for (int n = 0; n < NT; n++) {
            int c = nw * NT * 8 + n * 8 + lt * 2;
#pragma unroll
            for (int h = 0; h < 2; h++) {
                int rr = r + h * 8;
                if (rr >= N_NODES) continue;
                float v0 = acc[m][n][h * 2], v1 = acc[m][n][h * 2 + 1];
                if (c < OUTD_F) {
                    *(__half2*)(g_uh + (size_t)rr * OUTD_F + c) = __floats2half2_rn(v0, v1);
                } else {
                    g_v[(size_t)rr * OUTD_F + c - OUTD_F]     = v0 + bias[c - OUTD_F];
                    g_v[(size_t)rr * OUTD_F + c - OUTD_F + 1] = v1 + bias[c - OUTD_F + 1];
                }
            }
        }
    }
}

// ---------------- fused: gather-mean(U bf16) + V, L2-norm, ReLU, bf16 ------
__global__ void k_aggnorm() {
    int warp = (blockIdx.x * blockDim.x + threadIdx.x) >> 5;
    int lane = threadIdx.x & 31;
    if (warp >= N_NODES) return;
    int n = warp;
    const uint2* __restrict__ U2 = (const uint2*)g_Ub;
    const int* __restrict__ csc = g_csc;
    int j = g_off[n], je = g_off[n + 1];
    float ax = 0.f, ay = 0.f, az = 0.f, aw = 0.f;

    int s0 = 0, s1 = 0, s2 = 0, s3 = 0;
    if (j + 3 < je) {
        s0 = __ldg(&csc[j]);     s1 = __ldg(&csc[j + 1]);
        s2 = __ldg(&csc[j + 2]); s3 = __ldg(&csc[j + 3]);
    }
    while (j + 3 < je) {
        uint2 w0 = __ldg(&U2[(size_t)s0 * 32 + lane]);
        uint2 w1 = __ldg(&U2[(size_t)s1 * 32 + lane]);
        uint2 w2 = __ldg(&U2[(size_t)s2 * 32 + lane]);
        uint2 w3 = __ldg(&U2[(size_t)s3 * 32 + lane]);
        int jn = j + 4;
        if (jn + 3 < je) {
            s0 = __ldg(&csc[jn]);     s1 = __ldg(&csc[jn + 1]);
            s2 = __ldg(&csc[jn + 2]); s3 = __ldg(&csc[jn + 3]);
        }
        ax += bf_lo(w0.x) + bf_lo(w1.x) + bf_lo(w2.x) + bf_lo(w3.x);
        ay += bf_hi(w0.x) + bf_hi(w1.x) + bf_hi(w2.x) + bf_hi(w3.x);
        az += bf_lo(w0.y) + bf_lo(w1.y) + bf_lo(w2.y) + bf_lo(w3.y);
        aw += bf_hi(w0.y) + bf_hi(w1.y) + bf_hi(w2.y) + bf_hi(w3.y);
        j = jn;
    }
    for (; j < je; j++) {
        uint2 w0 = __ldg(&U2[(size_t)__ldg(&csc[j]) * 32 + lane]);
        ax += bf_lo(w0.x); ay += bf_hi(w0.x);
        az += bf_lo(w0.y); aw += bf_hi(w0.y);
    }
    float inv_d = g_invdeg[n];
    float4 vv = ((const float4*)g_V)[(size_t)n * 32 + lane];
    ax = ax * inv_d + vv.x;
    ay = ay * inv_d + vv.y;
    az = az * inv_d + vv.z;
    aw = aw * inv_d + vv.w;

    float ss = ax * ax + ay * ay + az * az + aw * aw;
#pragma unroll
    for (int s = 16; s; s >>= 1) ss += __shfl_xor_sync(0xFFFFFFFFu, ss, s);
    float sc = 1.0f / fmaxf(sqrtf(ss), 1e-12f);
    ax = fmaxf(ax * sc, 0.f);
    ay = fmaxf(ay * sc, 0.f);
    az = fmaxf(az * sc, 0.f);
    aw = fmaxf(aw * sc, 0.f);

    size_t widx = ((size_t)n * DIMF + lane * 4) >> 1;
    unsigned* xo = (unsigned*)g_xhi;
    xo[widx]     = bf_pack(ax, ay);
    xo[widx + 1] = bf_pack(az, aw);
}

// ---------------- layer-2: gather u(fp16), add v, softmax ------------------
__global__ void k_agg_softmax(float* __restrict__ out) {
    int warp = (blockIdx.x * blockDim.x + threadIdx.x) >> 5;
    int lane = threadIdx.x & 31;
    if (warp >= N_NODES) return;
    int n = warp;
    bool act = lane < 20;
    const __half2* __restrict__ u2 = (const __half2*)g_uh;
    const int* __restrict__ csc = g_csc;
    int j = g_off[n], je = g_off[n + 1];
    float acc0 = 0.f, acc1 = 0.f;

    int s0 = 0, s1 = 0, s2 = 0, s3 = 0;
    if (j + 3 < je) {
        s0 = __ldg(&csc[j]);     s1 = __ldg(&csc[j + 1]);
        s2 = __ldg(&csc[j + 2]); s3 = __ldg(&csc[j + 3]);
    }
    while (j + 3 < je) {
        float2 f0, f1, f2, f3;
        if (act) {
            f0 = __half22float2(__ldg(&u2[(size_t)s0 * 20 + lane]));
            f1 = __half22float2(__ldg(&u2[(size_t)s1 * 20 + lane]));
            f2 = __half22float2(__ldg(&u2[(size_t)s2 * 20 + lane]));
            f3 = __half22float2(__ldg(&u2[(size_t)s3 * 20 + lane]));
        }
        int jn = j + 4;
        if (jn + 3 < je) {
            s0 = __ldg(&csc[jn]);     s1 = __ldg(&csc[jn + 1]);
            s2 = __ldg(&csc[jn + 2]); s3 = __ldg(&csc[jn + 3]);
        }
        if (act) {
            acc0 += f0.x + f1.x + f2.x + f3.x;
            acc1 += f0.y + f1.y + f2.y + f3.y;
        }
        j = jn;
    }
    for (; j < je; j++) {
        int s = __ldg(&csc[j]);
        if (act) {
            float2 f0 = __half22float2(__ldg(&u2[(size_t)s * 20 + lane]));
            acc0 += f0.x; acc1 += f0.y;
        }
    }
    float inv_d = g_invdeg[n];
    float a0 = -1e30f, a1 = -1e30f;
    if (act) {
        a0 = acc0 * inv_d + g_v[(size_t)n * OUTD_F + lane * 2];
        a1 = acc1 * inv_d + g_v[(size_t)n * OUTD_F + lane * 2 + 1];
    }
    float m = fmaxf(a0, a1);
#pragma unroll
    for (int s = 16; s; s >>= 1) m = fmaxf(m, __shfl_xor_sync(0xFFFFFFFFu, m, s));
    float e0 = act ? __expf(a0 - m) : 0.f;
    float e1 = act ? __expf(a1 - m) : 0.f;
    float sum = e0 + e1;
#pragma unroll
    for (int s = 16; s; s >>= 1) sum += __shfl_xor_sync(0xFFFFFFFFu, sum, s);
    float inv = 1.0f / sum;
    if (act) {
        float* row = out + (size_t)n * OUTD_F + lane * 2;
        row[0] = e0 * inv;
        row[1] = e1 * inv;
    }
}

// ---------------- launch ----------------------------------------------------
extern "C" void kernel_launch(void* const* d_in, const int* in_sizes, int n_in,
                              void* d_out, int out_size) {
    const float* x   = (const float*)d_in[0];
    const int*   e32 = (const int*)d_in[1];
    const float* Wl0 = (const float*)d_in[2];
    const float* Wr0 = (const float*)d_in[3];
    const float* b0  = (const float*)d_in[4];
    const float* Wl1 = (const float*)d_in[5];
    const float* Wr1 = (const float*)d_in[6];
    const float* b1  = (const float*)d_in[7];
    const float* Wl2 = (const float*)d_in[8];
    const float* Wr2 = (const float*)d_in[9];
    const float* b2  = (const float*)d_in[10];
    float* out = (float*)d_out;

    const int TB = 256;
    int nblk_nodes = (N_NODES + TB - 1) / TB;
    int nblk_edges = (N_EDGES + TB - 1) / TB;
    int nblk_gemm  = (N_NODES + 127) / 128;    // 782
    int nblk_wnode = (N_NODES + 7) / 8;        // warp-per-node
    int nblk_w     = (DIMF * DIMF + TB - 1) / TB;

    // fork a side stream for the CSC build (independent of layer-0 GEMM).
    // streams/events intentionally leaked (destroying mid-capture is illegal).
    cudaStream_t side;
    cudaEvent_t evFork, evCsc;
    cudaStreamCreateWithFlags(&side, cudaStreamNonBlocking);
    cudaEventCreateWithFlags(&evFork, cudaEventDisableTiming);
    cudaEventCreateWithFlags(&evCsc, cudaEventDisableTiming);

    cudaEventRecord(evFork, 0);
    cudaStreamWaitEvent(side, evFork, 0);

    // ---- side stream: dtype detect + CSC build ----
    k_detect<<<1, TB, 0, side>>>(e32);
    k_zero_deg<<<nblk_nodes, TB, 0, side>>>();
    k_hist<<<nblk_edges, TB, 0, side>>>(e32);
    k_scan1<<<NB_SCAN, SCAN_B, 0, side>>>();
    k_scan2<<<1, 128, 0, side>>>();
    k_scan3<<<nblk_nodes, TB, 0, side>>>();
    k_fill_csc<<<nblk_edges, TB, 0, side>>>(e32);
    cudaEventRecord(evCsc, side);

    // ---- main stream: weight rounding (1 launch) + fused layer-0 GEMM ----
    k_round_w<<<nblk_w, TB>>>(Wl0, Wr0, Wl1, Wr1, Wl2, Wr2);
    k_gemm_l01<true><<<nblk_gemm, TB>>>(x, b0, 0);

    // ---- join: aggnorm needs CSC + U/V ----
    cudaStreamWaitEvent(0, evCsc, 0);
    k_aggnorm<<<nblk_wnode, TB>>>();

    // ---- layer 1 ----
    k_gemm_l01<false><<<nblk_gemm, TB>>>(nullptr, b1, 1);
    k_aggnorm<<<nblk_wnode, TB>>>();

    // ---- layer 2 ----
    k_gemm2<<<nblk_gemm, TB>>>(b2);
    k_agg_softmax<<<nblk_wnode, TB>>>(out);
}

// round 17
// speedup vs baseline: 1.0495x; 1.0495x over previous
#include <cuda_runtime.h>
#include <cuda_bf16.h>
#include <cuda_fp16.h>
#include <math.h>

#define N_NODES 100000
#define N_EDGES 1600000
#define DIMF    128
#define OUTD_F  40
#define SCAN_B  1024
#define NB_SCAN 98   // ceil(100000/1024)

// ---------------- scratch (device globals; no allocation allowed) ----------
__device__ int   g_is64;
__device__ int   g_deg[N_NODES];
__device__ float g_invdeg[N_NODES];
__device__ int   g_off[N_NODES + 1];
__device__ int   g_cursor[N_NODES];
__device__ int   g_bsums[NB_SCAN];
__device__ int   g_csc[N_EDGES];
__device__ __align__(16) unsigned short g_Ub[(size_t)N_NODES * DIMF]; // X@Wl^T, bf16 bits
__device__ __align__(16) float  g_V [(size_t)N_NODES * DIMF];          // X@Wr^T + b
__device__ __align__(16) __half g_uh[(size_t)N_NODES * OUTD_F];        // layer2: h1@Wl2^T
__device__ __align__(16) float  g_v [(size_t)N_NODES * OUTD_F];        // layer2: h1@Wr2^T + b2
// activations + weights: single bf16 copies
__device__ __align__(16) __nv_bfloat16 g_xhi[(size_t)N_NODES * DIMF];
__device__ __align__(16) __nv_bfloat16 g_W0l[DIMF*DIMF], g_W0r[DIMF*DIMF];
__device__ __align__(16) __nv_bfloat16 g_W1l[DIMF*DIMF], g_W1r[DIMF*DIMF];
__device__ __align__(16) __nv_bfloat16 g_W2 [2*OUTD_F*DIMF];

__device__ __forceinline__ int edge_at(const int* __restrict__ e32, int i) {
    return g_is64 ? e32[2 * i] : e32[i];
}
__device__ __forceinline__ float bf_lo(unsigned w) { return __uint_as_float(w << 16); }
__device__ __forceinline__ float bf_hi(unsigned w) { return __uint_as_float(w & 0xFFFF0000u); }
__device__ __forceinline__ unsigned bf_pack(float a, float b) {
    return (unsigned)__bfloat16_as_ushort(__float2bfloat16(a)) |
           ((unsigned)__bfloat16_as_ushort(__float2bfloat16(b)) << 16);
}

// ---------------- init: zero degree + dtype detect (side-stream, fused) ----
__global__ void k_init(const int* __restrict__ e32) {
    int i = blockIdx.x * blockDim.x + threadIdx.x;
    if (i < N_NODES) g_deg[i] = 0;
    if (blockIdx.x == 0) {
        __shared__ int nz;
        if (threadIdx.x == 0) nz = 0;
        __syncthreads();
        for (int k = threadIdx.x; k < 1024; k += blockDim.x)
            if (e32[2 * k + 1] != 0) nz = 1;
        __syncthreads();
        if (threadIdx.x == 0) g_is64 = (nz == 0);
    }
}

// ---------------- graph preprocessing --------------------------------------
__global__ void k_hist(const int* __restrict__ e32) {
    int e = blockIdx.x * blockDim.x + threadIdx.x;
    if (e < N_EDGES) {
        int d = edge_at(e32, N_EDGES + e);
        if ((unsigned)d < N_NODES) atomicAdd(&g_deg[d], 1);
    }
}

__global__ void k_scan1() {
    __shared__ int sh[SCAN_B];
    int t = threadIdx.x;
    int i = blockIdx.x * SCAN_B + t;
    int v = (i < N_NODES) ? g_deg[i] : 0;
    sh[t] = v;
    __syncthreads();
    for (int s = 1; s < SCAN_B; s <<= 1) {
        int prev = (t >= s) ? sh[t - s] : 0;
        __syncthreads();
        sh[t] += prev;
        __syncthreads();
    }
    if (i < N_NODES) g_off[i] = sh[t] - v;
    if (t == SCAN_B - 1) g_bsums[blockIdx.x] = sh[t];
}

__global__ void k_scan2() {
    __shared__ int sh[128];
    int t = threadIdx.x;
    int v = (t < NB_SCAN) ? g_bsums[t] : 0;
    sh[t] = v;
    __syncthreads();
#pragma unroll
    for (int s = 1; s < 128; s <<= 1) {
        int prev = (t >= s) ? sh[t - s] : 0;
        __syncthreads();
        sh[t] += prev;
        __syncthreads();
    }
    if (t < NB_SCAN) g_bsums[t] = sh[t] - v;   // exclusive
}

__global__ void k_scan3() {
    int i = blockIdx.x * blockDim.x + threadIdx.x;
    if (i < N_NODES) {
        int o = g_off[i] + g_bsums[i >> 10];
        g_off[i] = o;
        g_cursor[i] = o;
        int d = g_deg[i];
        g_invdeg[i] = 1.0f / (float)(d > 1 ? d : 1);
    }
    if (i == 0) g_off[N_NODES] = N_EDGES;
}

__global__ void k_fill_csc(const int* __restrict__ e32) {
    int e = blockIdx.x * blockDim.x + threadIdx.x;
    if (e < N_EDGES) {
        int s = edge_at(e32, e);
        int d = edge_at(e32, N_EDGES + e);
        if ((unsigned)s < N_NODES && (unsigned)d < N_NODES) {
            int p = atomicAdd(&g_cursor[d], 1);
            g_csc[p] = s;
        }
    }
}

// ---------------- weight rounding: ALL layers, one launch -------------------
__global__ void k_round_w(const float* __restrict__ Wl0, const float* __restrict__ Wr0,
                          const float* __restrict__ Wl1, const float* __restrict__ Wr1,
                          const float* __restrict__ Wl2, const float* __restrict__ Wr2) {
    int i = blockIdx.x * blockDim.x + threadIdx.x;
    if (i < DIMF * DIMF) {
        g_W0l[i] = __float2bfloat16(Wl0[i]);
        g_W0r[i] = __float2bfloat16(Wr0[i]);
        g_W1l[i] = __float2bfloat16(Wl1[i]);
        g_W1r[i] = __float2bfloat16(Wr1[i]);
    }
    if (i < OUTD_F * DIMF) {
        g_W2[i]                 = __float2bfloat16(Wl2[i]);
        g_W2[OUTD_F * DIMF + i] = __float2bfloat16(Wr2[i]);
    }
}

// ---------------- tensor-core GEMM ------------------------------------------
__device__ __forceinline__ void mma_bf16(float* d, const unsigned* a, unsigned b0, unsigned b1) {
    asm volatile(
        "mma.sync.aligned.m16n8k16.row.col.f32.bf16.bf16.f32 "
        "{%0,%1,%2,%3}, {%4,%5,%6,%7}, {%8,%9}, {%0,%1,%2,%3};\n"
        : "+f"(d[0]), "+f"(d[1]), "+f"(d[2]), "+f"(d[3])
        : "r"(a[0]), "r"(a[1]), "r"(a[2]), "r"(a[3]), "r"(b0), "r"(b1));
}

// layers 0/1: blockIdx.y==0 -> U(bf16) = X@Wl^T ; ==1 -> V(f32) = X@Wr^T + b
// single-pass bf16. FP32A: layer 0 reads fp32 x directly.
template <bool FP32A>
__global__ void __launch_bounds__(256) k_gemm_l01(const float* __restrict__ xin,
                                                  const float* __restrict__ bias, int layer) {
    constexpr int OUTD = 128;
    constexpr int MT = 2, NT = 8, STR = 20;

    __shared__ __align__(16) unsigned sAh[128 * STR];
    __shared__ __align__(16) unsigned sWh[OUTD * STR];

    int side = blockIdx.y;
    const unsigned* Ah = (const unsigned*)g_xhi;
    const unsigned* Wh;
    if (layer == 0) Wh = (const unsigned*)(side ? g_W0r : g_W0l);
    else            Wh = (const unsigned*)(side ? g_W1r : g_W1l);

    int tid  = threadIdx.x;
    int wid  = tid >> 5, lane = tid & 31;
    int mw   = wid & 3, nw = wid >> 2;
    int row0 = blockIdx.x * 128;
    int lg   = lane >> 2, lt = lane & 3;

    float acc[MT][NT][4];
#pragma unroll
    for (int m = 0; m < MT; m++)
#pragma unroll
        for (int n = 0; n < NT; n++)
#pragma unroll
            for (int q = 0; q < 4; q++) acc[m][n][q] = 0.f;

#pragma unroll 1
    for (int kt = 0; kt < 4; kt++) {
        int kw = kt * 16;

        if (FP32A) {
#pragma unroll
            for (int i = tid; i < 1024; i += 256) {
                int r = i >> 3, q = (i & 7) * 4;
                float4 v = make_float4(0.f, 0.f, 0.f, 0.f);
                if (row0 + r < N_NODES)
                    v = *(const float4*)(xin + (size_t)(row0 + r) * DIMF + kt * 32 + q);
                int wq = q >> 1;
                sAh[r * STR + wq]     = bf_pack(v.x, v.y);
                sAh[r * STR + wq + 1] = bf_pack(v.z, v.w);
            }
        } else {
#pragma unroll
            for (int i = tid; i < 128 * 4; i += 256) {
                int r = i >> 2, q = (i & 3) * 4;
                uint4 vh = make_uint4(0, 0, 0, 0);
                if (row0 + r < N_NODES)
                    vh = *(const uint4*)(Ah + (size_t)(row0 + r) * 64 + kw + q);
                *(uint4*)(sAh + r * STR + q) = vh;
            }
        }
        for (int i = tid; i < OUTD * 4; i += 256) {
            int r = i >> 2, q = (i & 3) * 4;
            *(uint4*)(sWh + r * STR + q) = *(const uint4*)(Wh + (size_t)r * 64 + kw + q);
        }
        __syncthreads();

#pragma unroll
        for (int ks = 0; ks < 2; ks++) {
            int wb = ks * 8;
            unsigned ah[MT][4];
#pragma unroll
            for (int m = 0; m < MT; m++) {
                int rr = (mw * MT + m) * 16 + lg;
                ah[m][0] = sAh[rr * STR + wb + lt];
                ah[m][1] = sAh[(rr + 8) * STR + wb + lt];
                ah[m][2] = sAh[rr * STR + wb + 4 + lt];
                ah[m][3] = sAh[(rr + 8) * STR + wb + 4 + lt];
            }
#pragma unroll
            for (int n = 0; n < NT; n++) {
                int nr = nw * NT * 8 + n * 8 + lg;
                unsigned bh0 = sWh[nr * STR + wb + lt];
                unsigned bh1 = sWh[nr * STR + wb + 4 + lt];
#pragma unroll
                for (int m = 0; m < MT; m++)
                    mma_bf16(acc[m][n], ah[m], bh0, bh1);
            }
        }
        __syncthreads();
    }

#pragma unroll
    for (int m = 0; m < MT; m++) {
        int r = row0 + (mw * MT + m) * 16 + lg;
#pragma unroll
        for (int n = 0; n < NT; n++) {
            int c = nw * NT * 8 + n * 8 + lt * 2;
#pragma unroll
            for (int h = 0; h < 2; h++) {
                int rr = r + h * 8;
                if (rr >= N_NODES) continue;
                float v0 = acc[m][n][h * 2], v1 = acc[m][n][h * 2 + 1];
                if (side) {
                    g_V[(size_t)rr * OUTD + c]     = v0 + bias[c];
                    g_V[(size_t)rr * OUTD + c + 1] = v1 + bias[c + 1];
                } else {
                    *(unsigned*)(g_Ub + (size_t)rr * OUTD + c) = bf_pack(v0, v1);
                }
            }
        }
    }
}

// layer 2: [u|v] = h1 @ [Wl2;Wr2]^T; u -> fp16, v -> f32 + bias. single-pass.
__global__ void __launch_bounds__(256) k_gemm2(const float* __restrict__ bias) {
    constexpr int OUTD = 80;
    constexpr int MT = 2, NT = 5, STR = 20;

    __shared__ __align__(16) unsigned sAh[128 * STR];
    __shared__ __align__(16) unsigned sWh[OUTD * STR];

    int tid  = threadIdx.x;
    int wid  = tid >> 5, lane = tid & 31;
    int mw   = wid & 3, nw = wid >> 2;
    int row0 = blockIdx.x * 128;
    int lg   = lane >> 2, lt = lane & 3;

    float acc[MT][NT][4];
#pragma unroll
    for (int m = 0; m < MT; m++)
#pragma unroll
        for (int n = 0; n < NT; n++)
#pragma unroll
            for (int q = 0; q < 4; q++) acc[m][n][q] = 0.f;

    const unsigned* Ah = (const unsigned*)g_xhi;
    const unsigned* Wh = (const unsigned*)g_W2;

#pragma unroll 1
    for (int kt = 0; kt < 4; kt++) {
        int kw = kt * 16;

#pragma unroll
        for (int i = tid; i < 128 * 4; i += 256) {
            int r = i >> 2, q = (i & 3) * 4;
            uint4 vh = make_uint4(0, 0, 0, 0);
            if (row0 + r < N_NODES)
                vh = *(const uint4*)(Ah + (size_t)(row0 + r) * 64 + kw + q);
            *(uint4*)(sAh + r * STR + q) = vh;
        }
        for (int i = tid; i < OUTD * 4; i += 256) {
            int r = i >> 2, q = (i & 3) * 4;
            *(uint4*)(sWh + r * STR + q) = *(const uint4*)(Wh + (size_t)r * 64 + kw + q);
        }
        __syncthreads();

#pragma unroll
        for (int ks = 0; ks < 2; ks++) {
            int wb = ks * 8;
            unsigned ah[MT][4];
#pragma unroll
            for (int m = 0; m < MT; m++) {
                int rr = (mw * MT + m) * 16 + lg;
                ah[m][0] = sAh[rr * STR + wb + lt];
                ah[m][1] = sAh[(rr + 8) * STR + wb + lt];
                ah[m][2] = sAh[rr * STR + wb + 4 + lt];
                ah[m][3] = sAh[(rr + 8) * STR + wb + 4 + lt];
            }
#pragma unroll
            for (int n = 0; n < NT; n++) {
                int nr = nw * NT * 8 + n * 8 + lg;
                unsigned bh0 = sWh[nr * STR + wb + lt];
                unsigned bh1 = sWh[nr * STR + wb + 4 + lt];
#pragma unroll
                for (int m = 0; m < MT; m++)
                    mma_bf16(acc[m][n], ah[m], bh0, bh1);
            }
        }
        __syncthreads();
    }

#pragma unroll
    for (int m = 0; m < MT; m++) {
        int r = row0 + (mw * MT + m) * 16 + lg;
#pragma unroll
        for (int n = 0; n < NT; n++) {
            int c = nw * NT * 8 + n * 8 + lt * 2;
#pragma unroll
            for (int h = 0; h < 2; h++) {
                int rr = r + h * 8;
                if (rr >= N_NODES) continue;
                float v0 = acc[m][n][h * 2], v1 = acc[m][n][h * 2 + 1];
                if (c < OUTD_F) {
                    *(__half2*)(g_uh + (size_t)rr * OUTD_F + c) = __floats2half2_rn(v0, v1);
                } else {
                    g_v[(size_t)rr * OUTD_F + c - OUTD_F]     = v0 + bias[c - OUTD_F];
                    g_v[(size_t)rr * OUTD_F + c - OUTD_F + 1] = v1 + bias[c - OUTD_F + 1];
                }
            }
        }
    }
}

// ---------------- fused: gather-mean(U bf16) + V, L2-norm, ReLU, bf16 ------
__global__ void k_aggnorm() {
    int warp = (blockIdx.x * blockDim.x + threadIdx.x) >> 5;
    int lane = threadIdx.x & 31;
    if (warp >= N_NODES) return;
    int n = warp;
    const uint2* __restrict__ U2 = (const uint2*)g_Ub;
    const int* __restrict__ csc = g_csc;
    int j = g_off[n], je = g_off[n + 1];
    float ax = 0.f, ay = 0.f, az = 0.f, aw = 0.f;

    int s0 = 0, s1 = 0, s2 = 0, s3 = 0;
    if (j + 3 < je) {
        s0 = __ldg(&csc[j]);     s1 = __ldg(&csc[j + 1]);
        s2 = __ldg(&csc[j + 2]); s3 = __ldg(&csc[j + 3]);
    }
    while (j + 3 < je) {
        uint2 w0 = __ldg(&U2[(size_t)s0 * 32 + lane]);
        uint2 w1 = __ldg(&U2[(size_t)s1 * 32 + lane]);
        uint2 w2 = __ldg(&U2[(size_t)s2 * 32 + lane]);
        uint2 w3 = __ldg(&U2[(size_t)s3 * 32 + lane]);
        int jn = j + 4;
        if (jn + 3 < je) {
            s0 = __ldg(&csc[jn]);     s1 = __ldg(&csc[jn + 1]);
            s2 = __ldg(&csc[jn + 2]); s3 = __ldg(&csc[jn + 3]);
        }
        ax += bf_lo(w0.x) + bf_lo(w1.x) + bf_lo(w2.x) + bf_lo(w3.x);
        ay += bf_hi(w0.x) + bf_hi(w1.x) + bf_hi(w2.x) + bf_hi(w3.x);
        az += bf_lo(w0.y) + bf_lo(w1.y) + bf_lo(w2.y) + bf_lo(w3.y);
        aw += bf_hi(w0.y) + bf_hi(w1.y) + bf_hi(w2.y) + bf_hi(w3.y);
        j = jn;
    }
    for (; j < je; j++) {
        uint2 w0 = __ldg(&U2[(size_t)__ldg(&csc[j]) * 32 + lane]);
        ax += bf_lo(w0.x); ay += bf_hi(w0.x);
        az += bf_lo(w0.y); aw += bf_hi(w0.y);
    }
    float inv_d = g_invdeg[n];
    float4 vv = ((const float4*)g_V)[(size_t)n * 32 + lane];
    ax = ax * inv_d + vv.x;
    ay = ay * inv_d + vv.y;
    az = az * inv_d + vv.z;
    aw = aw * inv_d + vv.w;

    float ss = ax * ax + ay * ay + az * az + aw * aw;
#pragma unroll
    for (int s = 16; s; s >>= 1) ss += __shfl_xor_sync(0xFFFFFFFFu, ss, s);
    float sc = 1.0f / fmaxf(sqrtf(ss), 1e-12f);
    ax = fmaxf(ax * sc, 0.f);
    ay = fmaxf(ay * sc, 0.f);
    az = fmaxf(az * sc, 0.f);
    aw = fmaxf(aw * sc, 0.f);

    size_t widx = ((size_t)n * DIMF + lane * 4) >> 1;
    unsigned* xo = (unsigned*)g_xhi;
    xo[widx]     = bf_pack(ax, ay);
    xo[widx + 1] = bf_pack(az, aw);
}

// ---------------- layer-2: gather u(fp16), add v, softmax ------------------
__global__ void k_agg_softmax(float* __restrict__ out) {
    int warp = (blockIdx.x * blockDim.x + threadIdx.x) >> 5;
    int lane = threadIdx.x & 31;
    if (warp >= N_NODES) return;
    int n = warp;
    bool act = lane < 20;
    const __half2* __restrict__ u2 = (const __half2*)g_uh;
    const int* __restrict__ csc = g_csc;
    int j = g_off[n], je = g_off[n + 1];
    float acc0 = 0.f, acc1 = 0.f;

    int s0 = 0, s1 = 0, s2 = 0, s3 = 0;
    if (j + 3 < je) {
        s0 = __ldg(&csc[j]);     s1 = __ldg(&csc[j + 1]);
        s2 = __ldg(&csc[j + 2]); s3 = __ldg(&csc[j + 3]);
    }
    while (j + 3 < je) {
        float2 f0, f1, f2, f3;
        if (act) {
            f0 = __half22float2(__ldg(&u2[(size_t)s0 * 20 + lane]));
            f1 = __half22float2(__ldg(&u2[(size_t)s1 * 20 + lane]));
            f2 = __half22float2(__ldg(&u2[(size_t)s2 * 20 + lane]));
            f3 = __half22float2(__ldg(&u2[(size_t)s3 * 20 + lane]));
        }
        int jn = j + 4;
        if (jn + 3 < je) {
            s0 = __ldg(&csc[jn]);     s1 = __ldg(&csc[jn + 1]);
            s2 = __ldg(&csc[jn + 2]); s3 = __ldg(&csc[jn + 3]);
        }
        if (act) {
            acc0 += f0.x + f1.x + f2.x + f3.x;
            acc1 += f0.y + f1.y + f2.y + f3.y;
        }
        j = jn;
    }
    for (; j < je; j++) {
        int s = __ldg(&csc[j]);
        if (act) {
            float2 f0 = __half22float2(__ldg(&u2[(size_t)s * 20 + lane]));
            acc0 += f0.x; acc1 += f0.y;
        }
    }
    float inv_d = g_invdeg[n];
    float a0 = -1e30f, a1 = -1e30f;
    if (act) {
        a0 = acc0 * inv_d + g_v[(size_t)n * OUTD_F + lane * 2];
        a1 = acc1 * inv_d + g_v[(size_t)n * OUTD_F + lane * 2 + 1];
    }
    float m = fmaxf(a0, a1);
#pragma unroll
    for (int s = 16; s; s >>= 1) m = fmaxf(m, __shfl_xor_sync(0xFFFFFFFFu, m, s));
    float e0 = act ? __expf(a0 - m) : 0.f;
    float e1 = act ? __expf(a1 - m) : 0.f;
    float sum = e0 + e1;
#pragma unroll
    for (int s = 16; s; s >>= 1) sum += __shfl_xor_sync(0xFFFFFFFFu, sum, s);
    float inv = 1.0f / sum;
    if (act) {
        float* row = out + (size_t)n * OUTD_F + lane * 2;
        row[0] = e0 * inv;
        row[1] = e1 * inv;
    }
}

// ---------------- launch ----------------------------------------------------
extern "C" void kernel_launch(void* const* d_in, const int* in_sizes, int n_in,
                              void* d_out, int out_size) {
    const float* x   = (const float*)d_in[0];
    const int*   e32 = (const int*)d_in[1];
    const float* Wl0 = (const float*)d_in[2];
    const float* Wr0 = (const float*)d_in[3];
    const float* b0  = (const float*)d_in[4];
    const float* Wl1 = (const float*)d_in[5];
    const float* Wr1 = (const float*)d_in[6];
    const float* b1  = (const float*)d_in[7];
    const float* Wl2 = (const float*)d_in[8];
    const float* Wr2 = (const float*)d_in[9];
    const float* b2  = (const float*)d_in[10];
    float* out = (float*)d_out;

    const int TB = 256;
    int nblk_nodes = (N_NODES + TB - 1) / TB;
    int nblk_edges = (N_EDGES + TB - 1) / TB;
    int nblk_gemm  = (N_NODES + 127) / 128;    // 782
    int nblk_wnode = (N_NODES + 7) / 8;        // warp-per-node
    int nblk_w     = (DIMF * DIMF + TB - 1) / TB;

    // fork a side stream for the CSC build (independent of layer-0 GEMM).
    // streams/events intentionally leaked (destroying mid-capture is illegal).
    cudaStream_t side;
    cudaEvent_t evFork, evCsc;
    cudaStreamCreateWithFlags(&side, cudaStreamNonBlocking);
    cudaEventCreateWithFlags(&evFork, cudaEventDisableTiming);
    cudaEventCreateWithFlags(&evCsc, cudaEventDisableTiming);

    cudaEventRecord(evFork, 0);
    cudaStreamWaitEvent(side, evFork, 0);

    // ---- side stream: fused init (zero+detect) + CSC build (6 launches) ----
    k_init<<<nblk_nodes, TB, 0, side>>>(e32);
    k_hist<<<nblk_edges, TB, 0, side>>>(e32);
    k_scan1<<<NB_SCAN, SCAN_B, 0, side>>>();
    k_scan2<<<1, 128, 0, side>>>();
    k_scan3<<<nblk_nodes, TB, 0, side>>>();
    k_fill_csc<<<nblk_edges, TB, 0, side>>>(e32);
    cudaEventRecord(evCsc, side);

    // ---- main stream: weight rounding (1 launch) + layer-0 GEMM ----
    k_round_w<<<nblk_w, TB>>>(Wl0, Wr0, Wl1, Wr1, Wl2, Wr2);
    k_gemm_l01<true><<<dim3(nblk_gemm, 2), TB>>>(x, b0, 0);

    // ---- join: aggnorm needs CSC + U/V ----
    cudaStreamWaitEvent(0, evCsc, 0);
    k_aggnorm<<<nblk_wnode, TB>>>();

    // ---- layer 1 ----
    k_gemm_l01<false><<<dim3(nblk_gemm, 2), TB>>>(nullptr, b1, 1);
    k_aggnorm<<<nblk_wnode, TB>>>();

    // ---- layer 2 ----
    k_gemm2<<<nblk_gemm, TB>>>(b2);
    k_agg_softmax<<<nblk_wnode, TB>>>(out);
}